// round 15
// baseline (speedup 1.0000x reference)
#include <cuda_runtime.h>
#include <cstdint>

#define SIZE 8192
#define NB 64
#define BS 128

// g_h: fragment-packed intermediate: [k2][mt][cs][1024 grp][4]
__device__ float g_h[33554432];
// packed weights: w1p [kblk][cs][1024 grp][4], w2p [k2][nh][cs][512 grp][4]
__device__ float g_w1p[1048576];
__device__ float g_w2p[1048576];

__device__ __forceinline__ uint32_t smem_u32(const void* p) {
    uint32_t a;
    asm("{ .reg .u64 t; cvta.to.shared.u64 t, %1; cvt.u32.u64 %0, t; }" : "=r"(a) : "l"(p));
    return a;
}
__device__ __forceinline__ uint32_t f2tf(float f) {
    uint32_t r;
    asm("cvt.rna.tf32.f32 %0, %1;" : "=r"(r) : "f"(f));
    return r;
}
__device__ __forceinline__ float f2tff(float f) { return __uint_as_float(f2tf(f)); }
__device__ __forceinline__ void cpa16(uint32_t s, const float* g) {
    asm volatile("cp.async.cg.shared.global [%0], [%1], 16;" :: "r"(s), "l"(g));
}
__device__ __forceinline__ void sts_zero16(uint32_t s) {
    asm volatile("st.shared.v4.b32 [%0], {%1,%1,%1,%1};" :: "r"(s), "r"(0u));
}
#define CPA_COMMIT() asm volatile("cp.async.commit_group;" ::: "memory")
#define CPA_WAIT(n)  asm volatile("cp.async.wait_group %0;" :: "n"(n) : "memory")

__device__ __forceinline__ void mma8(float* d, const uint32_t* a, const uint32_t* b) {
    asm volatile(
        "mma.sync.aligned.m16n8k8.row.col.f32.tf32.tf32.f32 "
        "{%0,%1,%2,%3},{%4,%5,%6,%7},{%8,%9},{%0,%1,%2,%3};"
        : "+f"(d[0]), "+f"(d[1]), "+f"(d[2]), "+f"(d[3])
        : "r"(a[0]), "r"(a[1]), "r"(a[2]), "r"(a[3]), "r"(b[0]), "r"(b[1]));
}

// pass1 A pad (scalar LDS): 36%32==4 -> banks 4g+tg bijective
#define PA1 36
#define SMEM1 (3 * 128 * PA1 * 4)                  // 55296 B (A stages only)
#define SMEM2 (4 * 4096 * 4)                       // 65536 B (A stages only)
#define SMEMP (64 * 132 * 4 < 128 * 68 * 4 ? 128 * 68 * 4 : 64 * 132 * 4)  // prep

// ---------------- prep: pack tf32-rounded weights into fragment-group layout ----------------
__global__ void prep_pack(const float* __restrict__ w1, const float* __restrict__ w2) {
    extern __shared__ float ps[];
    int t = threadIdx.x;
    int cid = blockIdx.x;
    if (cid < 128) {
        int kblk = cid >> 1, h = cid & 1;
        const float4* src = (const float4*)(w1 + kblk * BS * BS + h * 64 * BS);
#pragma unroll
        for (int i = 0; i < 8; i++) {
            int idx = t + i * 256;            // 2048 float4 over [64 rows][128 cols]
            int row = idx >> 5, c4 = idx & 31;
            float4 v = src[idx];
            float4 o = make_float4(f2tff(v.x), f2tff(v.y), f2tff(v.z), f2tff(v.w));
            *(float4*)(ps + row * 132 + c4 * 4) = o;
        }
        __syncthreads();
#pragma unroll
        for (int i = 0; i < 8; i++) {
            int gidx = t + i * 256;           // 2048 groups over 2 cs
            int csl = gidx >> 10, grp = gidx & 1023;
            int cs = 2 * h + csl;
            int tg = grp & 3, g = (grp >> 2) & 7, wn = (grp >> 5) & 1, u = (grp >> 6) & 3, kk = grp >> 8;
            int rlo = csl * 32 + kk * 8 + tg, rhi = rlo + 4;     // local rows 0..63
            int l0 = wn * 64 + u * 16 + g;
            float4 o = make_float4(ps[rlo * 132 + l0], ps[rhi * 132 + l0],
                                   ps[rlo * 132 + l0 + 8], ps[rhi * 132 + l0 + 8]);
            *(float4*)(g_w1p + (size_t)(kblk * 4 + cs) * 4096 + grp * 4) = o;
        }
    } else {
        int k2 = (cid - 128) >> 1, nh = (cid - 128) & 1, q0 = nh * 32;
        const float* src = w2 + k2 * BS * BS;
#pragma unroll
        for (int i = 0; i < 8; i++) {
            int idx = t + i * 256;       // 2048 float4 over [128 rows][64 sel cols]
            int row = idx >> 4, c4 = idx & 15;
            int lc = c4 * 4;
            int sc = (lc < 32) ? (q0 + lc) : (32 + q0 + lc);
            float4 v = *(const float4*)(src + row * BS + sc);
            float4 o = make_float4(f2tff(v.x), f2tff(v.y), f2tff(v.z), f2tff(v.w));
            *(float4*)(ps + row * 68 + lc) = o;
        }
        __syncthreads();
#pragma unroll
        for (int i = 0; i < 8; i++) {
            int gidx = t + i * 256;      // 2048 groups
            int cs = gidx >> 9, grp = gidx & 511;
            int tg = grp & 3, g = (grp >> 2) & 7, wn = (grp >> 5) & 1, u = (grp >> 6) & 1, kk = grp >> 7;
            int rlo = cs * 16 + kk * 4 + tg, rhi = rlo + 64;
            int l0 = wn * 16 + u * 32 + g;
            float4 o = make_float4(ps[rlo * 68 + l0], ps[rhi * 68 + l0],
                                   ps[rlo * 68 + l0 + 8], ps[rhi * 68 + l0 + 8]);
            *(float4*)(g_w2p + (size_t)((k2 * 2 + nh) * 4 + cs) * 2048 + grp * 4) = o;
        }
    }
}

// ---------------- pass 1: CTA (kblk, mt). A staged via LDGSTS; B direct LDG.128 + 1-kk prefetch ----------------
__global__ void __launch_bounds__(256, 2) monarch_pass1(const float* __restrict__ X, int Btok, int nmt) {
    extern __shared__ float sm[];
    uint32_t sb = smem_u32(sm);

    int t = threadIdx.x, lane = t & 31, w = t >> 5;
    int kblk = blockIdx.x, mt = blockIdx.y, b0 = mt * 128;
    const float* xp = X + (size_t)b0 * SIZE + kblk * BS;

    int wm = w & 3, wn = w >> 2, g = lane >> 2, tg = lane & 3;
    int m0 = wm * 32;
    // per-lane B fragment base: float offset = kkg*1024 + u*256 + wn*128 + g*16 + tg*4
    const float* __restrict__ bW = g_w1p + (size_t)kblk * 4 * 4096 + wn * 128 + g * 16 + tg * 4;

#define P1_ISSUE_A(c) do { int st = (c) % 3;                                                 \
        uint32_t ab = sb + (uint32_t)(st * 128 * PA1) * 4;                                   \
        _Pragma("unroll")                                                                     \
        for (int i = 0; i < 4; i++) {                                                         \
            int p = t + i * 256;                                                              \
            int row = p >> 3, pc = p & 7;                                                     \
            uint32_t dst = ab + (uint32_t)(row * PA1 + pc * 4) * 4;                           \
            if (b0 + row < Btok) cpa16(dst, xp + (size_t)row * SIZE + (c) * 32 + pc * 4);     \
            else sts_zero16(dst);                                                             \
        }                                                                                     \
        CPA_COMMIT();                                                                         \
    } while (0)

    P1_ISSUE_A(0);
    P1_ISSUE_A(1);

    // preload B for kkg = 0
    uint4 bc[4], bn[4];
#pragma unroll
    for (int u = 0; u < 4; u++) bc[u] = *(const uint4*)(bW + u * 256);

    float d[2][8][4];
#pragma unroll
    for (int mi = 0; mi < 2; mi++)
#pragma unroll
        for (int s = 0; s < 8; s++)
#pragma unroll
            for (int j = 0; j < 4; j++) d[mi][s][j] = 0.f;

#pragma unroll
    for (int c = 0; c < 4; c++) {
        if (c == 3) { CPA_WAIT(0); } else { CPA_WAIT(1); }
        __syncthreads();
        if (c < 2) P1_ISSUE_A(c + 2);
        const float* Ab = sm + (c % 3) * 128 * PA1;
#pragma unroll
        for (int kk = 0; kk < 4; kk++) {
            int kkg = c * 4 + kk;
            if (kkg < 15) {
#pragma unroll
                for (int u = 0; u < 4; u++)
                    bn[u] = *(const uint4*)(bW + (kkg + 1) * 1024 + u * 256);
            }
            uint32_t a[2][4];
#pragma unroll
            for (int mi = 0; mi < 2; mi++) {
                int mb2 = m0 + mi * 16 + g, kb = kk * 8 + tg;
                a[mi][0] = f2tf(Ab[mb2 * PA1 + kb]);
                a[mi][1] = f2tf(Ab[(mb2 + 8) * PA1 + kb]);
                a[mi][2] = f2tf(Ab[mb2 * PA1 + kb + 4]);
                a[mi][3] = f2tf(Ab[(mb2 + 8) * PA1 + kb + 4]);
            }
#pragma unroll
            for (int u = 0; u < 4; u++) {
                uint32_t blo[2] = {bc[u].x, bc[u].y}, bhi[2] = {bc[u].z, bc[u].w};
                mma8(d[0][2 * u], a[0], blo);
                mma8(d[1][2 * u], a[1], blo);
                mma8(d[0][2 * u + 1], a[0], bhi);
                mma8(d[1][2 * u + 1], a[1], bhi);
            }
#pragma unroll
            for (int u = 0; u < 4; u++) bc[u] = bn[u];
        }
    }

    // epilogue: each (mi,s) is one full fragment group {d0,d2,d1,d3} -> STG.128 to g_h packed
    int kk1 = (kblk >> 2) & 3, tg1 = kblk & 3, cs1 = kblk >> 4;
#pragma unroll
    for (int mi = 0; mi < 2; mi++) {
        int grp = ((kk1 * 8 + wm * 2 + mi) * 8 + g) * 4 + tg1;
#pragma unroll
        for (int s = 0; s < 8; s++) {
            int k2 = wn * 32 + s * 4 + tg;
            size_t base = ((size_t)(k2 * nmt + mt) * 4 + cs1) * 4096;
            float4 o = make_float4(f2tff(d[mi][s][0]), f2tff(d[mi][s][2]),
                                   f2tff(d[mi][s][1]), f2tff(d[mi][s][3]));
            *(float4*)(g_h + base + grp * 4) = o;
        }
    }
}

// ---------------- pass 2: CTA (k2g, nh, mt). A staged (4-stage LDGSTS); B direct LDG + prefetch ----------------
__global__ void __launch_bounds__(256, 2) monarch_pass2(const float* __restrict__ bias,
                                                        float* __restrict__ OUT, int Btok, int nmt) {
    extern __shared__ float sm[];
    uint32_t sb = smem_u32(sm);
    __shared__ float4 bsh[32];

    int t = threadIdx.x, lane = t & 31, w = t >> 5;
    int k2g = blockIdx.x >> 1, nh = blockIdx.x & 1;
    int q0 = nh * 32;
    int mt = blockIdx.y, b0 = mt * 128;

    if (t < 32) bsh[t] = *(const float4*)(bias + (q0 + t) * BS + 4 * k2g);

    int wm = w & 3, wn = w >> 2, g = lane >> 2, tg = lane & 3;
    int m0 = wm * 32;
    // per-lane B fragment base: float offset = (kkg>>4)*16384 + (kkg&15)*512 + u*256 + wn*128+g*16+tg*4
    const float* __restrict__ bW = g_w2p + (size_t)(4 * k2g + nh) * 8192 + wn * 128 + g * 16 + tg * 4;

#define P2_ISSUE_A(cc) do { int st = (cc) & 3;                                                \
        int k2s = 2 * k2g + ((cc) >> 2); int cs = (cc) & 3;                                   \
        const float* ap = g_h + ((size_t)(k2s * nmt + mt) * 4 + cs) * 4096;                   \
        uint32_t ab = sb + (uint32_t)(st * 4096) * 4;                                         \
        _Pragma("unroll")                                                                      \
        for (int i = 0; i < 4; i++) {                                                          \
            int p = t + i * 256;                                                               \
            cpa16(ab + (uint32_t)p * 16, ap + p * 4);                                          \
        }                                                                                      \
        CPA_COMMIT();                                                                          \
    } while (0)

    P2_ISSUE_A(0);
    P2_ISSUE_A(1);
    P2_ISSUE_A(2);

    // preload B for kkg = 0
    uint4 bc[2], bn[2];
#pragma unroll
    for (int u = 0; u < 2; u++) bc[u] = *(const uint4*)(bW + u * 256);

    float d[2][2][4][4];
#pragma unroll
    for (int kl = 0; kl < 2; kl++)
#pragma unroll
        for (int mi = 0; mi < 2; mi++)
#pragma unroll
            for (int s = 0; s < 4; s++)
#pragma unroll
                for (int j = 0; j < 4; j++) d[kl][mi][s][j] = 0.f;

#pragma unroll
    for (int cc = 0; cc < 8; cc++) {
        if (cc < 6) { CPA_WAIT(2); } else if (cc == 6) { CPA_WAIT(1); } else { CPA_WAIT(0); }
        __syncthreads();
        if (cc < 5) P2_ISSUE_A(cc + 3);
        const float* Ab = sm + (cc & 3) * 4096;
        float (*dk)[4][4] = d[cc >> 2];
#pragma unroll
        for (int kk = 0; kk < 4; kk++) {
            int kkg = cc * 4 + kk;
            if (kkg < 31) {
                int kn = kkg + 1;
#pragma unroll
                for (int u = 0; u < 2; u++)
                    bn[u] = *(const uint4*)(bW + (kn >> 4) * 16384 + (kn & 15) * 512 + u * 256);
            }
            uint32_t a[2][4];
#pragma unroll
            for (int mi = 0; mi < 2; mi++) {
                uint4 av = *(const uint4*)(Ab + (((kk * 8 + wm * 2 + mi) * 8 + g) * 4 + tg) * 4);
                a[mi][0] = av.x; a[mi][1] = av.y; a[mi][2] = av.z; a[mi][3] = av.w;
            }
#pragma unroll
            for (int u = 0; u < 2; u++) {
                uint32_t blo[2] = {bc[u].x, bc[u].y}, bhi[2] = {bc[u].z, bc[u].w};
                mma8(dk[0][2 * u], a[0], blo);
                mma8(dk[1][2 * u], a[1], blo);
                mma8(dk[0][2 * u + 1], a[0], bhi);
                mma8(dk[1][2 * u + 1], a[1], bhi);
            }
#pragma unroll
            for (int u = 0; u < 2; u++) bc[u] = bn[u];
        }
    }

    // epilogue: float4 at out[row][q*128 + 4*k2g] + bias
#pragma unroll
    for (int mi = 0; mi < 2; mi++)
#pragma unroll
        for (int rh = 0; rh < 2; rh++) {
            int row = b0 + m0 + mi * 16 + g + rh * 8;
            if (row < Btok) {
                float* orow = OUT + (size_t)row * SIZE + 4 * k2g;
#pragma unroll
                for (int s2 = 0; s2 < 2; s2++)
#pragma unroll
                    for (int par = 0; par < 2; par++) {
                        int ql = wn * 16 + s2 * 8 + 2 * tg + par;   // 0..31
                        float4 bv = bsh[ql];
                        float4 o;
                        o.x = d[0][mi][s2][rh * 2 + par] + bv.x;
                        o.y = d[0][mi][s2 + 2][rh * 2 + par] + bv.y;
                        o.z = d[1][mi][s2][rh * 2 + par] + bv.z;
                        o.w = d[1][mi][s2 + 2][rh * 2 + par] + bv.w;
                        *(float4*)(orow + (size_t)(q0 + ql) * BS) = o;
                    }
            }
        }
}

// ---------------- launch ----------------
extern "C" void kernel_launch(void* const* d_in, const int* in_sizes, int n_in,
                              void* d_out, int out_size) {
    (void)n_in; (void)out_size;
    const float* x = (const float*)d_in[0];
    const float* w1 = (const float*)d_in[1];
    const float* w2 = (const float*)d_in[2];
    const float* bias = (const float*)d_in[3];
    float* out = (float*)d_out;
    int B = in_sizes[0] / SIZE;
    int mt = (B + 127) / 128;

    cudaFuncSetAttribute(prep_pack, cudaFuncAttributeMaxDynamicSharedMemorySize, SMEMP);
    cudaFuncSetAttribute(monarch_pass1, cudaFuncAttributeMaxDynamicSharedMemorySize, SMEM1);
    cudaFuncSetAttribute(monarch_pass2, cudaFuncAttributeMaxDynamicSharedMemorySize, SMEM2);

    prep_pack<<<256, 256, SMEMP>>>(w1, w2);
    monarch_pass1<<<dim3(NB, mt), 256, SMEM1>>>(x, B, mt);
    monarch_pass2<<<dim3(NB, mt), 256, SMEM2>>>(bias, out, B, mt);
}

// round 17
// speedup vs baseline: 1.2717x; 1.2717x over previous
#include <cuda_runtime.h>
#include <cstdint>

#define SIZE 8192
#define NB 64
#define BS 128

// g_h: fragment-packed intermediate: [k2][mt][cs][1024 quanta][4]
// quantum index: (kk*4+tg)*64 + (wm*2+mi)*8 + ((g+2*tg)&7)  (16B = one a-frag)
__device__ float g_h[33554432];
// packed weights: w1p [kblk][cs][1024 grp][4], w2p [k2][nh][cs][512 grp][4]
__device__ float g_w1p[1048576];
__device__ float g_w2p[1048576];

__device__ __forceinline__ uint32_t smem_u32(const void* p) {
    uint32_t a;
    asm("{ .reg .u64 t; cvta.to.shared.u64 t, %1; cvt.u32.u64 %0, t; }" : "=r"(a) : "l"(p));
    return a;
}
__device__ __forceinline__ uint32_t f2tf(float f) {
    uint32_t r;
    asm("cvt.rna.tf32.f32 %0, %1;" : "=r"(r) : "f"(f));
    return r;
}
__device__ __forceinline__ float f2tff(float f) { return __uint_as_float(f2tf(f)); }
__device__ __forceinline__ void cpa16(uint32_t s, const float* g) {
    asm volatile("cp.async.cg.shared.global [%0], [%1], 16;" :: "r"(s), "l"(g));
}
__device__ __forceinline__ void sts_zero16(uint32_t s) {
    asm volatile("st.shared.v4.b32 [%0], {%1,%1,%1,%1};" :: "r"(s), "r"(0u));
}
#define CPA_COMMIT() asm volatile("cp.async.commit_group;" ::: "memory")
#define CPA_WAIT(n)  asm volatile("cp.async.wait_group %0;" :: "n"(n) : "memory")

__device__ __forceinline__ void mma8(float* d, const uint32_t* a, const uint32_t* b) {
    asm volatile(
        "mma.sync.aligned.m16n8k8.row.col.f32.tf32.tf32.f32 "
        "{%0,%1,%2,%3},{%4,%5,%6,%7},{%8,%9},{%0,%1,%2,%3};"
        : "+f"(d[0]), "+f"(d[1]), "+f"(d[2]), "+f"(d[3])
        : "r"(a[0]), "r"(a[1]), "r"(a[2]), "r"(a[3]), "r"(b[0]), "r"(b[1]));
}

// pass1 A pad (scalar LDS): 36%32==4 -> banks 4g+tg bijective
#define PA1 36
#define SMEM1 ((3 * 128 * PA1 + 3 * 4096) * 4)     // 104448 B (2 CTAs/SM)
#define SMEM2 ((4 * 4096 + 4 * 2048) * 4)          // 98304 B  (2 CTAs/SM, 4-stage)
#define SMEMP (64 * 132 * 4 < 128 * 68 * 4 ? 128 * 68 * 4 : 64 * 132 * 4)  // prep

// ---------------- prep: pack tf32-rounded weights into fragment-group layout ----------------
__global__ void prep_pack(const float* __restrict__ w1, const float* __restrict__ w2) {
    extern __shared__ float ps[];
    int t = threadIdx.x;
    int cid = blockIdx.x;
    if (cid < 128) {
        int kblk = cid >> 1, h = cid & 1;
        const float4* src = (const float4*)(w1 + kblk * BS * BS + h * 64 * BS);
#pragma unroll
        for (int i = 0; i < 8; i++) {
            int idx = t + i * 256;            // 2048 float4 over [64 rows][128 cols]
            int row = idx >> 5, c4 = idx & 31;
            float4 v = src[idx];
            float4 o = make_float4(f2tff(v.x), f2tff(v.y), f2tff(v.z), f2tff(v.w));
            *(float4*)(ps + row * 132 + c4 * 4) = o;
        }
        __syncthreads();
#pragma unroll
        for (int i = 0; i < 8; i++) {
            int gidx = t + i * 256;           // 2048 groups over 2 cs
            int csl = gidx >> 10, grp = gidx & 1023;
            int cs = 2 * h + csl;
            int tg = grp & 3, g = (grp >> 2) & 7, wn = (grp >> 5) & 1, u = (grp >> 6) & 3, kk = grp >> 8;
            int rlo = csl * 32 + kk * 8 + tg, rhi = rlo + 4;     // local rows 0..63
            int l0 = wn * 64 + u * 16 + g;
            float4 o = make_float4(ps[rlo * 132 + l0], ps[rhi * 132 + l0],
                                   ps[rlo * 132 + l0 + 8], ps[rhi * 132 + l0 + 8]);
            *(float4*)(g_w1p + (size_t)(kblk * 4 + cs) * 4096 + grp * 4) = o;
        }
    } else {
        int k2 = (cid - 128) >> 1, nh = (cid - 128) & 1, q0 = nh * 32;
        const float* src = w2 + k2 * BS * BS;
#pragma unroll
        for (int i = 0; i < 8; i++) {
            int idx = t + i * 256;       // 2048 float4 over [128 rows][64 sel cols]
            int row = idx >> 4, c4 = idx & 15;
            int lc = c4 * 4;
            int sc = (lc < 32) ? (q0 + lc) : (32 + q0 + lc);
            float4 v = *(const float4*)(src + row * BS + sc);
            float4 o = make_float4(f2tff(v.x), f2tff(v.y), f2tff(v.z), f2tff(v.w));
            *(float4*)(ps + row * 68 + lc) = o;
        }
        __syncthreads();
#pragma unroll
        for (int i = 0; i < 8; i++) {
            int gidx = t + i * 256;      // 2048 groups
            int cs = gidx >> 9, grp = gidx & 511;
            int tg = grp & 3, g = (grp >> 2) & 7, wn = (grp >> 5) & 1, u = (grp >> 6) & 1, kk = grp >> 7;
            int rlo = cs * 16 + kk * 4 + tg, rhi = rlo + 64;
            int l0 = wn * 16 + u * 32 + g;
            float4 o = make_float4(ps[rlo * 68 + l0], ps[rhi * 68 + l0],
                                   ps[rlo * 68 + l0 + 8], ps[rhi * 68 + l0 + 8]);
            *(float4*)(g_w2p + (size_t)((k2 * 2 + nh) * 4 + cs) * 2048 + grp * 4) = o;
        }
    }
}

// ---------------- pass 1: CTA (kblk, mt): D[128 b][128 n], 3-stage cp.async, packed epilogue ----------------
__global__ void __launch_bounds__(256, 2) monarch_pass1(const float* __restrict__ X, int Btok, int nmt) {
    extern __shared__ float sm[];
    uint32_t sb = smem_u32(sm);

    int t = threadIdx.x, lane = t & 31, w = t >> 5;
    int kblk = blockIdx.x, mt = blockIdx.y, b0 = mt * 128;
    const float* xp = X + (size_t)b0 * SIZE + kblk * BS;
    const float* bp1 = g_w1p + (size_t)kblk * 4 * 4096;

#define P1_ISSUE(c) do { int st = (c) % 3;                                                   \
        uint32_t ab = sb + (uint32_t)(st * 128 * PA1) * 4;                                   \
        uint32_t bb = sb + (uint32_t)(3 * 128 * PA1 + st * 4096) * 4;                        \
        _Pragma("unroll")                                                                     \
        for (int i = 0; i < 4; i++) {                                                         \
            int p = t + i * 256;                                                              \
            int row = p >> 3, pc = p & 7;                                                     \
            uint32_t dst = ab + (uint32_t)(row * PA1 + pc * 4) * 4;                           \
            if (b0 + row < Btok) cpa16(dst, xp + (size_t)row * SIZE + (c) * 32 + pc * 4);     \
            else sts_zero16(dst);                                                             \
        }                                                                                     \
        _Pragma("unroll")                                                                     \
        for (int i = 0; i < 4; i++) {                                                         \
            int p = t + i * 256;                                                              \
            cpa16(bb + (uint32_t)p * 16, bp1 + (c) * 4096 + p * 4);                           \
        }                                                                                     \
        CPA_COMMIT();                                                                         \
    } while (0)

    P1_ISSUE(0);
    P1_ISSUE(1);

    int wm = w & 3, wn = w >> 2, g = lane >> 2, tg = lane & 3;
    int m0 = wm * 32;

    float d[2][8][4];
#pragma unroll
    for (int mi = 0; mi < 2; mi++)
#pragma unroll
        for (int s = 0; s < 8; s++)
#pragma unroll
            for (int j = 0; j < 4; j++) d[mi][s][j] = 0.f;

#pragma unroll
    for (int c = 0; c < 4; c++) {
        if (c == 3) { CPA_WAIT(0); } else { CPA_WAIT(1); }
        __syncthreads();
        if (c < 2) P1_ISSUE(c + 2);
        const float* Ab = sm + (c % 3) * 128 * PA1;
        const float* Bb = sm + 3 * 128 * PA1 + (c % 3) * 4096;
#pragma unroll
        for (int kk = 0; kk < 4; kk++) {
            uint32_t a[2][4];
#pragma unroll
            for (int mi = 0; mi < 2; mi++) {
                int mb = m0 + mi * 16 + g, kb = kk * 8 + tg;
                a[mi][0] = f2tf(Ab[mb * PA1 + kb]);
                a[mi][1] = f2tf(Ab[(mb + 8) * PA1 + kb]);
                a[mi][2] = f2tf(Ab[mb * PA1 + kb + 4]);
                a[mi][3] = f2tf(Ab[(mb + 8) * PA1 + kb + 4]);
            }
#pragma unroll
            for (int u = 0; u < 4; u++) {
                uint4 bv = *(const uint4*)(Bb + ((((kk * 4 + u) * 2 + wn) * 8 + g) * 4 + tg) * 4);
                uint32_t blo[2] = {bv.x, bv.y}, bhi[2] = {bv.z, bv.w};
                mma8(d[0][2 * u], a[0], blo);
                mma8(d[1][2 * u], a[1], blo);
                mma8(d[0][2 * u + 1], a[0], bhi);
                mma8(d[1][2 * u + 1], a[1], bhi);
            }
        }
    }

    // epilogue: fragment quanta {d0,d2,d1,d3} -> g_h, layout giving full-line CTA writes:
    // qidx = (kk1*4+tg1)*64 + (wm*2+mi)*8 + ((g+2*tg1)&7)
    int kk1 = (kblk >> 2) & 3, tg1 = kblk & 3, cs1 = kblk >> 4;
    int gperm = (g + 2 * tg1) & 7;
#pragma unroll
    for (int mi = 0; mi < 2; mi++) {
        int qidx = (kk1 * 4 + tg1) * 64 + (wm * 2 + mi) * 8 + gperm;
#pragma unroll
        for (int s = 0; s < 8; s++) {
            int k2 = wn * 32 + s * 4 + tg;
            size_t base = ((size_t)(k2 * nmt + mt) * 4 + cs1) * 4096;
            float4 o = make_float4(f2tff(d[mi][s][0]), f2tff(d[mi][s][2]),
                                   f2tff(d[mi][s][1]), f2tff(d[mi][s][3]));
            *(float4*)(g_h + base + qidx * 4) = o;
        }
    }
}

// ---------------- pass 2: CTA (k2g, nh, mt): k2 pair, 8 packed chunks, 4-stage pipeline ----------------
__global__ void __launch_bounds__(256, 2) monarch_pass2(const float* __restrict__ bias,
                                                        float* __restrict__ OUT, int Btok, int nmt) {
    extern __shared__ float sm[];
    uint32_t sb = smem_u32(sm);
    __shared__ float4 bsh[32];

    int t = threadIdx.x, lane = t & 31, w = t >> 5;
    int k2g = blockIdx.x >> 1, nh = blockIdx.x & 1;
    int q0 = nh * 32;
    int mt = blockIdx.y, b0 = mt * 128;

    if (t < 32) bsh[t] = *(const float4*)(bias + (q0 + t) * BS + 4 * k2g);

#define P2_ISSUE(cc) do { int st = (cc) & 3;                                                  \
        int k2s = 2 * k2g + ((cc) >> 2); int cs = (cc) & 3;                                   \
        const float* ap = g_h + ((size_t)(k2s * nmt + mt) * 4 + cs) * 4096;                   \
        const float* bp = g_w2p + (size_t)((k2s * 2 + nh) * 4 + cs) * 2048;                   \
        uint32_t ab = sb + (uint32_t)(st * 4096) * 4;                                         \
        uint32_t bb = sb + (uint32_t)(4 * 4096 + st * 2048) * 4;                              \
        _Pragma("unroll")                                                                      \
        for (int i = 0; i < 4; i++) {                                                          \
            int p = t + i * 256;                                                               \
            cpa16(ab + (uint32_t)p * 16, ap + p * 4);                                          \
        }                                                                                      \
        _Pragma("unroll")                                                                      \
        for (int i = 0; i < 2; i++) {                                                          \
            int p = t + i * 256;                                                               \
            cpa16(bb + (uint32_t)p * 16, bp + p * 4);                                          \
        }                                                                                      \
        CPA_COMMIT();                                                                          \
    } while (0)

    P2_ISSUE(0);
    P2_ISSUE(1);
    P2_ISSUE(2);

    int wm = w & 3, wn = w >> 2, g = lane >> 2, tg = lane & 3;
    int m0 = wm * 32;
    int gperm2 = (g + 2 * tg) & 7;          // matches pass1's write permutation

    float d[2][2][4][4];
#pragma unroll
    for (int kl = 0; kl < 2; kl++)
#pragma unroll
        for (int mi = 0; mi < 2; mi++)
#pragma unroll
            for (int s = 0; s < 4; s++)
#pragma unroll
                for (int j = 0; j < 4; j++) d[kl][mi][s][j] = 0.f;

#pragma unroll
    for (int cc = 0; cc < 8; cc++) {
        if (cc < 6) { CPA_WAIT(2); } else if (cc == 6) { CPA_WAIT(1); } else { CPA_WAIT(0); }
        __syncthreads();
        if (cc < 5) P2_ISSUE(cc + 3);
        const float* Ab = sm + (cc & 3) * 4096;
        const float* Bb = sm + 4 * 4096 + (cc & 3) * 2048;
        float (*dk)[4][4] = d[cc >> 2];
#pragma unroll
        for (int kk = 0; kk < 4; kk++) {
            uint32_t a[2][4];
#pragma unroll
            for (int mi = 0; mi < 2; mi++) {
                int qidx = (kk * 4 + tg) * 64 + (wm * 2 + mi) * 8 + gperm2;
                uint4 av = *(const uint4*)(Ab + qidx * 4);
                a[mi][0] = av.x; a[mi][1] = av.y; a[mi][2] = av.z; a[mi][3] = av.w;
            }
#pragma unroll
            for (int u = 0; u < 2; u++) {
                uint4 bv = *(const uint4*)(Bb + ((((kk * 2 + u) * 2 + wn) * 8 + g) * 4 + tg) * 4);
                uint32_t blo[2] = {bv.x, bv.y}, bhi[2] = {bv.z, bv.w};
                mma8(dk[0][2 * u], a[0], blo);
                mma8(dk[1][2 * u], a[1], blo);
                mma8(dk[0][2 * u + 1], a[0], bhi);
                mma8(dk[1][2 * u + 1], a[1], bhi);
            }
        }
    }

    // epilogue: float4 at out[row][q*128 + 4*k2g] + bias
#pragma unroll
    for (int mi = 0; mi < 2; mi++)
#pragma unroll
        for (int rh = 0; rh < 2; rh++) {
            int row = b0 + m0 + mi * 16 + g + rh * 8;
            if (row < Btok) {
                float* orow = OUT + (size_t)row * SIZE + 4 * k2g;
#pragma unroll
                for (int s2 = 0; s2 < 2; s2++)
#pragma unroll
                    for (int par = 0; par < 2; par++) {
                        int ql = wn * 16 + s2 * 8 + 2 * tg + par;   // 0..31
                        float4 bv = bsh[ql];
                        float4 o;
                        o.x = d[0][mi][s2][rh * 2 + par] + bv.x;
                        o.y = d[0][mi][s2 + 2][rh * 2 + par] + bv.y;
                        o.z = d[1][mi][s2][rh * 2 + par] + bv.z;
                        o.w = d[1][mi][s2 + 2][rh * 2 + par] + bv.w;
                        *(float4*)(orow + (size_t)(q0 + ql) * BS) = o;
                    }
            }
        }
}

// ---------------- launch ----------------
extern "C" void kernel_launch(void* const* d_in, const int* in_sizes, int n_in,
                              void* d_out, int out_size) {
    (void)n_in; (void)out_size;
    const float* x = (const float*)d_in[0];
    const float* w1 = (const float*)d_in[1];
    const float* w2 = (const float*)d_in[2];
    const float* bias = (const float*)d_in[3];
    float* out = (float*)d_out;
    int B = in_sizes[0] / SIZE;
    int mt = (B + 127) / 128;

    cudaFuncSetAttribute(prep_pack, cudaFuncAttributeMaxDynamicSharedMemorySize, SMEMP);
    cudaFuncSetAttribute(monarch_pass1, cudaFuncAttributeMaxDynamicSharedMemorySize, SMEM1);
    cudaFuncSetAttribute(monarch_pass2, cudaFuncAttributeMaxDynamicSharedMemorySize, SMEM2);

    prep_pack<<<256, 256, SMEMP>>>(w1, w2);
    monarch_pass1<<<dim3(NB, mt), 256, SMEM1>>>(x, B, mt);
    monarch_pass2<<<dim3(NB, mt), 256, SMEM2>>>(bias, out, B, mt);
}